// round 2
// baseline (speedup 1.0000x reference)
#include <cuda_runtime.h>
#include <math.h>

// ---------------------------------------------------------------------------
// Problem constants
// ---------------------------------------------------------------------------
#define C_DIM   192
#define NH      6
#define HD      32
#define NTOK    64          // tokens per window
#define NWIN    4096        // total windows (B * 1024)
#define M_TOT   262144      // NWIN * NTOK == B*H*W tokens
#define HIDDEN  768
#define QKV_N   576
#define SCALE_F 0.17677669529663687f   // 32^-0.5

// ---------------------------------------------------------------------------
// Scratch (static device globals: allowed; runtime allocation is not)
// ---------------------------------------------------------------------------
__device__ float g_qkv [(size_t)M_TOT * QKV_N];   // 604 MB
__device__ float g_attn[(size_t)M_TOT * C_DIM];   // 201 MB
__device__ float g_tmp [(size_t)M_TOT * C_DIM];   // proj_img, later fc2 out
__device__ float g_x1  [(size_t)M_TOT * C_DIM];
__device__ float g_h   [(size_t)M_TOT * HIDDEN];  // 805 MB

// ---------------------------------------------------------------------------
// window-layout row -> image-layout row (cyclic shift by +4 folded in).
// Same bijection for gather (forward) and scatter (reverse).
// ---------------------------------------------------------------------------
__device__ __forceinline__ int map_row(int m) {
    int w    = m >> 6;          // window id
    int t    = m & 63;          // token in window
    int b    = w >> 10;
    int widx = w & 1023;
    int wh   = widx >> 5;
    int ww   = widx & 31;
    int r    = t >> 3;
    int c    = t & 7;
    int h    = (wh * 8 + r + 4) & 255;
    int wc   = (ww * 8 + c + 4) & 255;
    return (b << 16) | (h << 8) | wc;   // b*65536 + h*256 + wc
}

// ---------------------------------------------------------------------------
// Generic fp32 GEMM:  C[m,n] = sum_k A[m,k] * W[n,k] + bias[n]
// BM=64, BN=64, BK=16, 256 threads, 4x4 register blocking.
// GATHER: A rows indexed through map_row (A = x in image layout)
// SCATTER: C rows indexed through map_row (C in image layout)
// DOGELU: exact gelu epilogue
// ---------------------------------------------------------------------------
template<bool GATHER, bool SCATTER, bool DOGELU>
__global__ __launch_bounds__(256) void gemm_k(
    const float* __restrict__ A, const float* __restrict__ W,
    const float* __restrict__ bias, float* __restrict__ C,
    int N, int K)
{
    __shared__ __align__(16) float As[16][68];
    __shared__ __align__(16) float Bs[16][68];

    const int tid     = threadIdx.x;
    const int rowBase = blockIdx.y * 64;
    const int colBase = blockIdx.x * 64;

    const int lr = tid >> 2;          // 0..63  (row within tile to load)
    const int lk = (tid & 3) << 2;    // 0,4,8,12

    int arow = rowBase + lr;
    if (GATHER) arow = map_row(arow);
    const float* aPtr = A + (size_t)arow * K + lk;
    const float* bPtr = W + (size_t)(colBase + lr) * K + lk;

    const int tm = (tid >> 4) << 2;   // 0..60
    const int tn = (tid & 15) << 2;   // 0..60

    float acc[4][4] = {};

    for (int k0 = 0; k0 < K; k0 += 16) {
        float4 av = *(const float4*)(aPtr + k0);
        float4 bv = *(const float4*)(bPtr + k0);
        As[lk + 0][lr] = av.x; As[lk + 1][lr] = av.y;
        As[lk + 2][lr] = av.z; As[lk + 3][lr] = av.w;
        Bs[lk + 0][lr] = bv.x; Bs[lk + 1][lr] = bv.y;
        Bs[lk + 2][lr] = bv.z; Bs[lk + 3][lr] = bv.w;
        __syncthreads();
        #pragma unroll
        for (int k = 0; k < 16; k++) {
            float4 a4 = *(const float4*)&As[k][tm];
            float4 b4 = *(const float4*)&Bs[k][tn];
            float ar[4] = {a4.x, a4.y, a4.z, a4.w};
            float br[4] = {b4.x, b4.y, b4.z, b4.w};
            #pragma unroll
            for (int i = 0; i < 4; i++)
                #pragma unroll
                for (int j = 0; j < 4; j++)
                    acc[i][j] = fmaf(ar[i], br[j], acc[i][j]);
        }
        __syncthreads();
    }

    #pragma unroll
    for (int i = 0; i < 4; i++) {
        int crow = rowBase + tm + i;
        if (SCATTER) crow = map_row(crow);
        float* cp = C + (size_t)crow * N + colBase + tn;
        #pragma unroll
        for (int j = 0; j < 4; j++) {
            float v = acc[i][j] + bias[colBase + tn + j];
            if (DOGELU) v = 0.5f * v * (1.0f + erff(v * 0.70710678118654752f));
            cp[j] = v;
        }
    }
}

// ---------------------------------------------------------------------------
// Attention: one block per (window, head). 64 threads = 64 query rows.
// ---------------------------------------------------------------------------
__global__ __launch_bounds__(64) void attn_k(
    const float* __restrict__ qkv, const float* __restrict__ rpb_table,
    const int* __restrict__ rel_idx, const float* __restrict__ mask,
    float* __restrict__ outp)
{
    const int blk = blockIdx.x;
    const int w   = blk / NH;
    const int hh  = blk % NH;
    const int t    = threadIdx.x;     // 0..63 (query row)
    const int lane = t & 31;
    const int wrp  = t >> 5;

    __shared__ float Qs[64][33];
    __shared__ float Ks[64][33];
    __shared__ float Vs[64][33];

    const size_t rowbase = (size_t)w * 64;
    // coalesced cooperative loads: one warp per row, 32 floats per row
    for (int j = wrp; j < 64; j += 2) {
        const float* p = qkv + (rowbase + j) * QKV_N + hh * HD + lane;
        Qs[j][lane] = p[0];
        Ks[j][lane] = p[192];
        Vs[j][lane] = p[384];
    }
    __syncthreads();

    float q[32];
    #pragma unroll
    for (int d = 0; d < 32; d++) q[d] = Qs[t][d];

    float s[64];
    #pragma unroll 4
    for (int j = 0; j < 64; j++) {
        float a = 0.f;
        #pragma unroll
        for (int d = 0; d < 32; d++) a = fmaf(q[d], Ks[j][d], a);
        s[j] = a * SCALE_F;
    }

    const float* mrow = mask + ((w & 1023) * 4096 + t * 64);
    const int*   rrow = rel_idx + t * 64;
    float mx = -1e30f;
    #pragma unroll 4
    for (int j = 0; j < 64; j++) {
        s[j] += rpb_table[rrow[j] * NH + hh] + mrow[j];
        mx = fmaxf(mx, s[j]);
    }
    float sum = 0.f;
    #pragma unroll 4
    for (int j = 0; j < 64; j++) { s[j] = expf(s[j] - mx); sum += s[j]; }
    const float inv = 1.f / sum;

    float o[32] = {};
    #pragma unroll 4
    for (int j = 0; j < 64; j++) {
        float p = s[j] * inv;
        #pragma unroll
        for (int d = 0; d < 32; d++) o[d] = fmaf(p, Vs[j][d], o[d]);
    }

    float* op = outp + (rowbase + t) * C_DIM + hh * HD;
    #pragma unroll
    for (int d = 0; d < 32; d += 4)
        *(float4*)(op + d) = make_float4(o[d], o[d+1], o[d+2], o[d+3]);
}

// ---------------------------------------------------------------------------
// LayerNorm(y)*g+b + res   -- one warp per token (C=192 -> 6 elems/lane)
// ---------------------------------------------------------------------------
__global__ __launch_bounds__(256) void ln_res_k(
    const float* __restrict__ y, const float* __restrict__ res,
    const float* __restrict__ g, const float* __restrict__ b,
    float* __restrict__ outp)
{
    const size_t token = (size_t)blockIdx.x * 8 + (threadIdx.x >> 5);
    const int lane = threadIdx.x & 31;
    const float* yr = y + token * C_DIM;

    float v[6];
    float sum = 0.f;
    #pragma unroll
    for (int i = 0; i < 6; i++) { v[i] = yr[lane + 32 * i]; sum += v[i]; }
    #pragma unroll
    for (int o = 16; o; o >>= 1) sum += __shfl_xor_sync(0xffffffffu, sum, o);
    const float mu = sum * (1.f / 192.f);

    float sq = 0.f;
    #pragma unroll
    for (int i = 0; i < 6; i++) { float d = v[i] - mu; sq = fmaf(d, d, sq); }
    #pragma unroll
    for (int o = 16; o; o >>= 1) sq += __shfl_xor_sync(0xffffffffu, sq, o);
    const float inv = rsqrtf(sq * (1.f / 192.f) + 1e-5f);

    const float* rr = res + token * C_DIM;
    float* op = outp + token * C_DIM;
    #pragma unroll
    for (int i = 0; i < 6; i++) {
        int c = lane + 32 * i;
        op[c] = rr[c] + (v[i] - mu) * inv * g[c] + b[c];
    }
}

// ---------------------------------------------------------------------------
// Launch
// ---------------------------------------------------------------------------
extern "C" void kernel_launch(void* const* d_in, const int* in_sizes, int n_in,
                              void* d_out, int out_size)
{
    const float* x      = (const float*)d_in[0];
    const float* mask   = (const float*)d_in[1];
    const int*   relidx = (const int*)  d_in[2];
    const float* qkv_w  = (const float*)d_in[3];
    const float* qkv_b  = (const float*)d_in[4];
    const float* proj_w = (const float*)d_in[5];
    const float* proj_b = (const float*)d_in[6];
    const float* rpb    = (const float*)d_in[7];
    const float* n1g    = (const float*)d_in[8];
    const float* n1b    = (const float*)d_in[9];
    const float* n2g    = (const float*)d_in[10];
    const float* n2b    = (const float*)d_in[11];
    const float* fc1w   = (const float*)d_in[12];
    const float* fc1b   = (const float*)d_in[13];
    const float* fc2w   = (const float*)d_in[14];
    const float* fc2b   = (const float*)d_in[15];
    float* out = (float*)d_out;

    float *qkv_s, *attn_s, *tmp_s, *x1_s, *h_s;
    cudaGetSymbolAddress((void**)&qkv_s,  g_qkv);
    cudaGetSymbolAddress((void**)&attn_s, g_attn);
    cudaGetSymbolAddress((void**)&tmp_s,  g_tmp);
    cudaGetSymbolAddress((void**)&x1_s,   g_x1);
    cudaGetSymbolAddress((void**)&h_s,    g_h);

    // 1. shift+window gather fused into qkv GEMM: [262144,192]x[192,576]
    gemm_k<true, false, false><<<dim3(QKV_N / 64, M_TOT / 64), 256>>>(
        x, qkv_w, qkv_b, qkv_s, QKV_N, C_DIM);

    // 2. windowed attention
    attn_k<<<NWIN * NH, 64>>>(qkv_s, rpb, relidx, mask, attn_s);

    // 3. proj GEMM + scatter back to image layout
    gemm_k<false, true, false><<<dim3(C_DIM / 64, M_TOT / 64), 256>>>(
        attn_s, proj_w, proj_b, tmp_s, C_DIM, C_DIM);

    // 4. x1 = x + LN1(proj_img)
    ln_res_k<<<M_TOT / 8, 256>>>(tmp_s, x, n1g, n1b, x1_s);

    // 5. fc1 + exact GELU: [262144,192]x[192,768]
    gemm_k<false, false, true><<<dim3(HIDDEN / 64, M_TOT / 64), 256>>>(
        x1_s, fc1w, fc1b, h_s, HIDDEN, C_DIM);

    // 6. fc2: [262144,768]x[768,192]
    gemm_k<false, false, false><<<dim3(C_DIM / 64, M_TOT / 64), 256>>>(
        h_s, fc2w, fc2b, tmp_s, C_DIM, HIDDEN);

    // 7. out = x1 + LN2(fc2_out)
    ln_res_k<<<M_TOT / 8, 256>>>(tmp_s, x1_s, n2g, n2b, out);
}

// round 4
// speedup vs baseline: 2.0375x; 2.0375x over previous
#include <cuda_runtime.h>
#include <cuda_bf16.h>
#include <math.h>
#include <stdint.h>

// ---------------------------------------------------------------------------
// Problem constants
// ---------------------------------------------------------------------------
#define C_DIM   192
#define NH      6
#define HD      32
#define NWIN    4096
#define M_TOT   262144
#define HIDDEN  768
#define QKV_N   576
#define SCALE_F 0.17677669529663687f

// ---------------------------------------------------------------------------
// Scratch
// ---------------------------------------------------------------------------
__device__ float g_qkv [(size_t)M_TOT * QKV_N];
__device__ float g_attn[(size_t)M_TOT * C_DIM];
__device__ float g_tmp [(size_t)M_TOT * C_DIM];
__device__ float g_x1  [(size_t)M_TOT * C_DIM];
__device__ float g_h   [(size_t)M_TOT * HIDDEN];

// ---------------------------------------------------------------------------
// shift/window row bijection
// ---------------------------------------------------------------------------
__device__ __forceinline__ int map_row(int m) {
    int w    = m >> 6;
    int t    = m & 63;
    int b    = w >> 10;
    int widx = w & 1023;
    int wh   = widx >> 5;
    int ww   = widx & 31;
    int r    = t >> 3;
    int c    = t & 7;
    int h    = (wh * 8 + r + 4) & 255;
    int wc   = (ww * 8 + c + 4) & 255;
    return (b << 16) | (h << 8) | wc;
}

__device__ __forceinline__ uint32_t smem_to_u32(const void* p) {
    uint32_t a;
    asm("{ .reg .u64 t; cvta.to.shared.u64 t, %1; cvt.u32.u64 %0, t; }" : "=r"(a) : "l"(p));
    return a;
}

#define LDM_X4(r0, r1, r2, r3, addr) \
    asm volatile("ldmatrix.sync.aligned.m8n8.x4.shared.b16 {%0,%1,%2,%3}, [%4];" \
                 : "=r"(r0), "=r"(r1), "=r"(r2), "=r"(r3) : "r"(addr))

#define MMA_BF16(d, a, b) \
    asm volatile("mma.sync.aligned.m16n8k16.row.col.f32.bf16.bf16.f32 " \
                 "{%0,%1,%2,%3}, {%4,%5,%6,%7}, {%8,%9}, {%0,%1,%2,%3};" \
                 : "+f"((d)[0]), "+f"((d)[1]), "+f"((d)[2]), "+f"((d)[3]) \
                 : "r"((a)[0]), "r"((a)[1]), "r"((a)[2]), "r"((a)[3]), \
                   "r"((b)[0]), "r"((b)[1]))

__device__ __forceinline__ uint32_t pk_bf2(float x, float y) {
    __nv_bfloat162 t = __floats2bfloat162_rn(x, y);
    return *(uint32_t*)&t;
}

// ---------------------------------------------------------------------------
// mma.sync GEMM:  C[m,n] = sum_k A[m,k] W[n,k] + bias[n]
// bf16 3-term split (AhWh + AhWl + AlWh), fp32 accumulate.
// BM=128, BN=64, BK=32, 256 threads, warps 4(M) x 2(N), warp tile 32x32.
// ---------------------------------------------------------------------------
#define BM 128
#define BN 64
#define BK 32
// smem layout per stage (bytes):
//   Ah [128][40]h @0      (10240)
//   Al [128][40]h @10240  (10240)
//   Bh [64][40]h  @20480  (5120)
//   Bl [64][40]h  @25600  (5120)
#define SST      30720
#define MM_SMEM  (2 * SST)

template<bool GATHER, bool SCATTER, bool DOGELU>
__global__ __launch_bounds__(256, 2) void mm_hmma(
    const float* __restrict__ A, const float* __restrict__ W,
    const float* __restrict__ bias, float* __restrict__ Cc,
    int N, int K)
{
    extern __shared__ char sm[];
    const uint32_t sbase = smem_to_u32(sm);

    const int tid   = threadIdx.x;
    const int wid   = tid >> 5;
    const int lane  = tid & 31;
    const int warpM = wid & 3;       // 0..3
    const int warpN = wid >> 2;      // 0..1
    const int rowBase = blockIdx.y * BM;
    const int colBase = blockIdx.x * BN;

    const int nch = K / BK;

    // ---- per-thread staging coordinates ----
    // A: 1024 float4 (128 rows x 8 float4), 4 per thread
    // B: 512  float4 (64  rows x 8 float4), 2 per thread
    int aRow[4], aOffB[4];
    const float* aPtr[4];
    #pragma unroll
    for (int i = 0; i < 4; i++) {
        int idx = tid + i * 256;
        int row = idx >> 3, c4 = idx & 7;
        int ar = rowBase + row;
        if (GATHER) ar = map_row(ar);
        aPtr[i]  = A + (size_t)ar * K + c4 * 4;
        aRow[i]  = row;
        aOffB[i] = row * 80 + c4 * 8;
    }
    const float* bPtr[2];
    int bOffB[2];
    #pragma unroll
    for (int i = 0; i < 2; i++) {
        int idx = tid + i * 256;
        int row = idx >> 3, c4 = idx & 7;
        bPtr[i]  = W + (size_t)(colBase + row) * K + c4 * 4;
        bOffB[i] = 20480 + row * 80 + c4 * 8;
    }

    float4 av[4], bv[2];

    auto ldg_tile = [&](int k0) {
        #pragma unroll
        for (int i = 0; i < 4; i++) av[i] = *(const float4*)(aPtr[i] + k0);
        #pragma unroll
        for (int i = 0; i < 2; i++) bv[i] = *(const float4*)(bPtr[i] + k0);
    };
    auto sts_tile = [&](int s) {
        char* base = sm + s * SST;
        #pragma unroll
        for (int i = 0; i < 4; i++) {
            float4 v = av[i];
            float hx = __bfloat162float(__float2bfloat16_rn(v.x));
            float hy = __bfloat162float(__float2bfloat16_rn(v.y));
            float hz = __bfloat162float(__float2bfloat16_rn(v.z));
            float hw = __bfloat162float(__float2bfloat16_rn(v.w));
            uint2 hi = make_uint2(pk_bf2(v.x, v.y), pk_bf2(v.z, v.w));
            uint2 lo = make_uint2(pk_bf2(v.x - hx, v.y - hy), pk_bf2(v.z - hz, v.w - hw));
            *(uint2*)(base + aOffB[i])         = hi;
            *(uint2*)(base + 10240 + aOffB[i]) = lo;
        }
        #pragma unroll
        for (int i = 0; i < 2; i++) {
            float4 v = bv[i];
            float hx = __bfloat162float(__float2bfloat16_rn(v.x));
            float hy = __bfloat162float(__float2bfloat16_rn(v.y));
            float hz = __bfloat162float(__float2bfloat16_rn(v.z));
            float hw = __bfloat162float(__float2bfloat16_rn(v.w));
            uint2 hi = make_uint2(pk_bf2(v.x, v.y), pk_bf2(v.z, v.w));
            uint2 lo = make_uint2(pk_bf2(v.x - hx, v.y - hy), pk_bf2(v.z - hz, v.w - hw));
            *(uint2*)(base + bOffB[i])        = hi;
            *(uint2*)(base + 5120 + bOffB[i]) = lo;
        }
    };

    // ldmatrix source addresses (term-relative, byte offsets added per use)
    // A tile (m16k16): row = warpM*32 + mt*16 + (lane&15), col = kk + (lane>>4)*8
    const uint32_t aRowL = (uint32_t)(warpM * 32 + (lane & 15));
    const uint32_t aColL = (uint32_t)((lane >> 4) * 8);
    // B tile (n16k16): row = warpN*32 + nt2*16 + (lane&7) + ((lane>>4)<<3),
    //                  col = kk + ((lane>>3)&1)*8
    const uint32_t bRowL = (uint32_t)(warpN * 32 + (lane & 7) + ((lane >> 4) << 3));
    const uint32_t bColL = (uint32_t)(((lane >> 3) & 1) * 8);

    float acc[2][4][4] = {};   // [mt][nt][4]

    ldg_tile(0);
    sts_tile(0);
    __syncthreads();

    for (int it = 0; it < nch; it++) {
        const int s = it & 1;
        if (it + 1 < nch) ldg_tile((it + 1) * BK);

        const uint32_t stg = sbase + s * SST;
        #pragma unroll
        for (int kk = 0; kk < BK; kk += 16) {
            uint32_t ah[2][4], al[2][4], bh[2][4], bl[2][4];
            #pragma unroll
            for (int mt = 0; mt < 2; mt++) {
                uint32_t off = (aRowL + mt * 16) * 80 + (aColL + kk) * 2;
                LDM_X4(ah[mt][0], ah[mt][1], ah[mt][2], ah[mt][3], stg + off);
                LDM_X4(al[mt][0], al[mt][1], al[mt][2], al[mt][3], stg + 10240 + off);
            }
            #pragma unroll
            for (int nt2 = 0; nt2 < 2; nt2++) {
                uint32_t off = 20480 + (bRowL + nt2 * 16) * 80 + (bColL + kk) * 2;
                LDM_X4(bh[nt2][0], bh[nt2][1], bh[nt2][2], bh[nt2][3], stg + off);
                LDM_X4(bl[nt2][0], bl[nt2][1], bl[nt2][2], bl[nt2][3], stg + 5120 + off);
            }
            #pragma unroll
            for (int mt = 0; mt < 2; mt++) {
                #pragma unroll
                for (int nt = 0; nt < 4; nt++) {
                    uint32_t bfh[2] = { bh[nt >> 1][(nt & 1) * 2], bh[nt >> 1][(nt & 1) * 2 + 1] };
                    uint32_t bfl[2] = { bl[nt >> 1][(nt & 1) * 2], bl[nt >> 1][(nt & 1) * 2 + 1] };
                    MMA_BF16(acc[mt][nt], ah[mt], bfh);
                    MMA_BF16(acc[mt][nt], ah[mt], bfl);
                    MMA_BF16(acc[mt][nt], al[mt], bfh);
                }
            }
        }
        __syncthreads();
        if (it + 1 < nch) {
            sts_tile((it + 1) & 1);
            __syncthreads();
        }
    }

    // ---- epilogue ----
    const int qid = lane >> 2;
    const int cid = (lane & 3) * 2;
    #pragma unroll
    for (int mt = 0; mt < 2; mt++) {
        #pragma unroll
        for (int half2i = 0; half2i < 2; half2i++) {
            int row = rowBase + warpM * 32 + mt * 16 + qid + half2i * 8;
            if (SCATTER) row = map_row(row);
            float* cp = Cc + (size_t)row * N;
            #pragma unroll
            for (int nt = 0; nt < 4; nt++) {
                int col = colBase + warpN * 32 + nt * 8 + cid;
                float2 bvv = *(const float2*)(bias + col);
                float2 o;
                o.x = acc[mt][nt][half2i * 2 + 0] + bvv.x;
                o.y = acc[mt][nt][half2i * 2 + 1] + bvv.y;
                if (DOGELU) {
                    o.x = 0.5f * o.x * (1.0f + erff(o.x * 0.70710678118654752f));
                    o.y = 0.5f * o.y * (1.0f + erff(o.y * 0.70710678118654752f));
                }
                *(float2*)(cp + col) = o;
            }
        }
    }
}

// ---------------------------------------------------------------------------
// Attention: one block per (window, head), 64 threads = 64 query rows.
// ---------------------------------------------------------------------------
__global__ __launch_bounds__(64) void attn_k(
    const float* __restrict__ qkv, const float* __restrict__ rpb_table,
    const int* __restrict__ rel_idx, const float* __restrict__ mask,
    float* __restrict__ outp)
{
    const int blk = blockIdx.x;
    const int w   = blk / NH;
    const int hh  = blk % NH;
    const int t    = threadIdx.x;
    const int lane = t & 31;
    const int wrp  = t >> 5;

    __shared__ float Qs[64][33];
    __shared__ float Ks[64][33];
    __shared__ float Vs[64][33];

    const size_t rowbase = (size_t)w * 64;
    for (int j = wrp; j < 64; j += 2) {
        const float* p = qkv + (rowbase + j) * QKV_N + hh * HD + lane;
        Qs[j][lane] = p[0];
        Ks[j][lane] = p[192];
        Vs[j][lane] = p[384];
    }
    __syncthreads();

    float q[32];
    #pragma unroll
    for (int d = 0; d < 32; d++) q[d] = Qs[t][d];

    float s[64];
    #pragma unroll 4
    for (int j = 0; j < 64; j++) {
        float a = 0.f;
        #pragma unroll
        for (int d = 0; d < 32; d++) a = fmaf(q[d], Ks[j][d], a);
        s[j] = a * SCALE_F;
    }

    const float* mrow = mask + ((w & 1023) * 4096 + t * 64);
    const int*   rrow = rel_idx + t * 64;
    float mx = -1e30f;
    #pragma unroll 4
    for (int j = 0; j < 64; j++) {
        s[j] += rpb_table[rrow[j] * NH + hh] + mrow[j];
        mx = fmaxf(mx, s[j]);
    }
    float sum = 0.f;
    #pragma unroll 4
    for (int j = 0; j < 64; j++) { s[j] = expf(s[j] - mx); sum += s[j]; }
    const float inv = 1.f / sum;

    float o[32] = {};
    #pragma unroll 4
    for (int j = 0; j < 64; j++) {
        float p = s[j] * inv;
        #pragma unroll
        for (int d = 0; d < 32; d++) o[d] = fmaf(p, Vs[j][d], o[d]);
    }

    float* op = outp + (rowbase + t) * C_DIM + hh * HD;
    #pragma unroll
    for (int d = 0; d < 32; d += 4)
        *(float4*)(op + d) = make_float4(o[d], o[d+1], o[d+2], o[d+3]);
}

// ---------------------------------------------------------------------------
// LayerNorm(y)*g+b + res
// ---------------------------------------------------------------------------
__global__ __launch_bounds__(256) void ln_res_k(
    const float* __restrict__ y, const float* __restrict__ res,
    const float* __restrict__ g, const float* __restrict__ b,
    float* __restrict__ outp)
{
    const size_t token = (size_t)blockIdx.x * 8 + (threadIdx.x >> 5);
    const int lane = threadIdx.x & 31;
    const float* yr = y + token * C_DIM;

    float v[6];
    float sum = 0.f;
    #pragma unroll
    for (int i = 0; i < 6; i++) { v[i] = yr[lane + 32 * i]; sum += v[i]; }
    #pragma unroll
    for (int o = 16; o; o >>= 1) sum += __shfl_xor_sync(0xffffffffu, sum, o);
    const float mu = sum * (1.f / 192.f);

    float sq = 0.f;
    #pragma unroll
    for (int i = 0; i < 6; i++) { float d = v[i] - mu; sq = fmaf(d, d, sq); }
    #pragma unroll
    for (int o = 16; o; o >>= 1) sq += __shfl_xor_sync(0xffffffffu, sq, o);
    const float inv = rsqrtf(sq * (1.f / 192.f) + 1e-5f);

    const float* rr = res + token * C_DIM;
    float* op = outp + token * C_DIM;
    #pragma unroll
    for (int i = 0; i < 6; i++) {
        int c = lane + 32 * i;
        op[c] = rr[c] + (v[i] - mu) * inv * g[c] + b[c];
    }
}

// ---------------------------------------------------------------------------
// Launch
// ---------------------------------------------------------------------------
extern "C" void kernel_launch(void* const* d_in, const int* in_sizes, int n_in,
                              void* d_out, int out_size)
{
    const float* x      = (const float*)d_in[0];
    const float* mask   = (const float*)d_in[1];
    const int*   relidx = (const int*)  d_in[2];
    const float* qkv_w  = (const float*)d_in[3];
    const float* qkv_b  = (const float*)d_in[4];
    const float* proj_w = (const float*)d_in[5];
    const float* proj_b = (const float*)d_in[6];
    const float* rpb    = (const float*)d_in[7];
    const float* n1g    = (const float*)d_in[8];
    const float* n1b    = (const float*)d_in[9];
    const float* n2g    = (const float*)d_in[10];
    const float* n2b    = (const float*)d_in[11];
    const float* fc1w   = (const float*)d_in[12];
    const float* fc1b   = (const float*)d_in[13];
    const float* fc2w   = (const float*)d_in[14];
    const float* fc2b   = (const float*)d_in[15];
    float* out = (float*)d_out;

    float *qkv_s, *attn_s, *tmp_s, *x1_s, *h_s;
    cudaGetSymbolAddress((void**)&qkv_s,  g_qkv);
    cudaGetSymbolAddress((void**)&attn_s, g_attn);
    cudaGetSymbolAddress((void**)&tmp_s,  g_tmp);
    cudaGetSymbolAddress((void**)&x1_s,   g_x1);
    cudaGetSymbolAddress((void**)&h_s,    g_h);

    cudaFuncSetAttribute(mm_hmma<true,  false, false>, cudaFuncAttributeMaxDynamicSharedMemorySize, MM_SMEM);
    cudaFuncSetAttribute(mm_hmma<false, true,  false>, cudaFuncAttributeMaxDynamicSharedMemorySize, MM_SMEM);
    cudaFuncSetAttribute(mm_hmma<false, false, true >, cudaFuncAttributeMaxDynamicSharedMemorySize, MM_SMEM);
    cudaFuncSetAttribute(mm_hmma<false, false, false>, cudaFuncAttributeMaxDynamicSharedMemorySize, MM_SMEM);

    // 1. gather + qkv GEMM
    mm_hmma<true, false, false><<<dim3(QKV_N / BN, M_TOT / BM), 256, MM_SMEM>>>(
        x, qkv_w, qkv_b, qkv_s, QKV_N, C_DIM);

    // 2. windowed attention
    attn_k<<<NWIN * NH, 64>>>(qkv_s, rpb, relidx, mask, attn_s);

    // 3. proj GEMM + scatter to image layout
    mm_hmma<false, true, false><<<dim3(C_DIM / BN, M_TOT / BM), 256, MM_SMEM>>>(
        attn_s, proj_w, proj_b, tmp_s, C_DIM, C_DIM);

    // 4. x1 = x + LN1(proj_img)
    ln_res_k<<<M_TOT / 8, 256>>>(tmp_s, x, n1g, n1b, x1_s);

    // 5. fc1 + GELU
    mm_hmma<false, false, true><<<dim3(HIDDEN / BN, M_TOT / BM), 256, MM_SMEM>>>(
        x1_s, fc1w, fc1b, h_s, HIDDEN, C_DIM);

    // 6. fc2
    mm_hmma<false, false, false><<<dim3(C_DIM / BN, M_TOT / BM), 256, MM_SMEM>>>(
        h_s, fc2w, fc2b, tmp_s, C_DIM, HIDDEN);

    // 7. out = x1 + LN2(fc2_out)
    ln_res_k<<<M_TOT / 8, 256>>>(tmp_s, x1_s, n2g, n2b, out);
}